// round 14
// baseline (speedup 1.0000x reference)
#include <cuda_runtime.h>
#include <cuda_fp16.h>
#include <cstdint>

// ---------------- problem dims ----------------
#define BBX   4
#define SSZ   1024
#define DDM   1024
#define HHX   16
#define DFF   4096
#define ROWS  4096          // BBX*SSZ
#define BHH   64            // BBX*HHX
#define QKVLD 3072
#define SAW   72            // GEMM smem stride (halfs) for BK=64

// flash-attention smem strides (halfs)
#define LDQ   72
#define LDK   72
#define LDV   72            // V staged [s][d]; transposed in ldmatrix
#define QSZ   (128 * LDQ)
#define KSZ   (128 * LDK)
#define VSZ   (128 * LDV)
#define FL_SMEM (2 * (QSZ + 2 * KSZ + 2 * VSZ) + 4096)   // 96256 bytes

// GEMM smem: block tile 128(M) x 256(N), BK=64, 3 stages
#define G_ASZ (128 * SAW * 2)        // 18432 B
#define G_BSZ (256 * SAW * 2)        // 36864 B
#define G_STG (G_ASZ + G_BSZ)        // 55296 B
#define G_SMEM (3 * G_STG)           // 165888 B

// ---------------- scratch (static device globals) ----------------
__device__ __half g_xn   [(size_t)ROWS * DDM];
__device__ __half g_qkv  [(size_t)ROWS * QKVLD];
__device__ __half g_ctx  [(size_t)ROWS * DDM];
__device__ float  g_x1   [(size_t)ROWS * DDM];
__device__ __half g_ff   [(size_t)ROWS * DFF];
__device__ __half g_wqkvt[(size_t)QKVLD * DDM];
__device__ __half g_wot  [(size_t)DDM * DDM];
__device__ __half g_w1t  [(size_t)DFF * DDM];
__device__ __half g_w2t  [(size_t)DDM * DFF];
__device__ float  g_bqkv [QKVLD];

// ---------------- helpers ----------------
__device__ __forceinline__ uint32_t smem_u32(const void* p) {
    uint32_t a;
    asm("{ .reg .u64 t; cvta.to.shared.u64 t, %1; cvt.u32.u64 %0, t; }"
        : "=r"(a) : "l"(p));
    return a;
}
__device__ __forceinline__ void cpasync16(uint32_t s, const void* g) {
    asm volatile("cp.async.cg.shared.global [%0], [%1], 16;" :: "r"(s), "l"(g));
}
#define CP_COMMIT() asm volatile("cp.async.commit_group;" ::: "memory")
#define CP_WAIT1()  asm volatile("cp.async.wait_group 1;" ::: "memory")
#define CP_WAIT0()  asm volatile("cp.async.wait_group 0;" ::: "memory")

__device__ __forceinline__ void ldsm4(uint32_t addr, uint32_t& r0, uint32_t& r1,
                                      uint32_t& r2, uint32_t& r3) {
    asm volatile("ldmatrix.sync.aligned.m8n8.x4.shared.b16 {%0,%1,%2,%3}, [%4];"
                 : "=r"(r0), "=r"(r1), "=r"(r2), "=r"(r3) : "r"(addr));
}
__device__ __forceinline__ void ldsm4t(uint32_t addr, uint32_t& r0, uint32_t& r1,
                                       uint32_t& r2, uint32_t& r3) {
    asm volatile("ldmatrix.sync.aligned.m8n8.x4.trans.shared.b16 {%0,%1,%2,%3}, [%4];"
                 : "=r"(r0), "=r"(r1), "=r"(r2), "=r"(r3) : "r"(addr));
}

__device__ __forceinline__ void mma_f16(float (&d)[4],
                                        const uint32_t (&a)[4],
                                        const uint32_t (&b)[2]) {
    asm volatile(
        "mma.sync.aligned.m16n8k16.row.col.f32.f16.f16.f32 "
        "{%0,%1,%2,%3},{%4,%5,%6,%7},{%8,%9},{%0,%1,%2,%3};"
        : "+f"(d[0]), "+f"(d[1]), "+f"(d[2]), "+f"(d[3])
        : "r"(a[0]), "r"(a[1]), "r"(a[2]), "r"(a[3]),
          "r"(b[0]), "r"(b[1]));
}

// ---------------- GEMM: cp.async tile loader (one BK=64 chunk, halfs) ----
// A: 128 rows, B: 256 rows; each row 64 halfs = 8 x 16B transfers
__device__ __forceinline__ void load_chunk64(const __half* __restrict__ A, int lda,
                                             const __half* __restrict__ B, int ldb,
                                             int k0, uint32_t sA, uint32_t sB, int tid)
{
    #pragma unroll
    for (int it = 0; it < 4; it++) {
        const int idx = tid + it * 256;
        const int r = idx >> 3, c = idx & 7;
        cpasync16(sA + (uint32_t)(r * SAW + c * 8) * 2,
                  A + (size_t)r * lda + k0 + c * 8);
    }
    #pragma unroll
    for (int it = 0; it < 8; it++) {
        const int idx = tid + it * 256;
        const int r = idx >> 3, c = idx & 7;
        cpasync16(sB + (uint32_t)(r * SAW + c * 8) * 2,
                  B + (size_t)r * ldb + k0 + c * 8);
    }
}

// fragment loads for one k16 step (A 64 rows, B 64 rows per warp)
__device__ __forceinline__ void ld_frags(uint32_t aB, uint32_t bB,
                                         uint32_t (&af)[4][4], uint32_t (&bf)[8][2])
{
    #pragma unroll
    for (int mi = 0; mi < 4; mi++)
        ldsm4(aB + (uint32_t)(mi * 16 * SAW) * 2,
              af[mi][0], af[mi][1], af[mi][2], af[mi][3]);
    #pragma unroll
    for (int np = 0; np < 4; np++)
        ldsm4(bB + (uint32_t)(np * 16 * SAW) * 2,
              bf[2 * np][0], bf[2 * np][1],
              bf[2 * np + 1][0], bf[2 * np + 1][1]);
}

#define MMA_BATCH(af, bf)                               \
    _Pragma("unroll")                                   \
    for (int mi = 0; mi < 4; mi++)                      \
        _Pragma("unroll")                               \
        for (int ni = 0; ni < 8; ni++)                  \
            mma_f16(acc[mi][ni], (af)[mi], (bf)[ni]);

// ---------------- GEMM mainloop: BK=64, 3 stages, frag double buffer ----
// warp tile 64x64: 8 warps as 2m x 4n over the 128x256 block tile
__device__ __forceinline__ void mma_mainloop(const __half* __restrict__ A, int lda,
                                             const __half* __restrict__ B, int ldb,
                                             int K, float (&acc)[4][8][4], char* dyn)
{
    const int tid = threadIdx.x;
    const int wid = tid >> 5, lane = tid & 31;
    const int wm = wid >> 2, wn = wid & 3;
    const uint32_t sbase = smem_u32(dyn);

    const uint32_t aOff = (uint32_t)(((wm * 64 + (lane & 15)) * SAW + ((lane >> 4) << 3)) * 2);
    const uint32_t bOff = (uint32_t)(((wn * 64 + (lane & 7) + ((lane >> 4) << 3)) * SAW
                                      + (((lane >> 3) & 1) << 3)) * 2);

    const int nk = K >> 6;
    load_chunk64(A, lda, B, ldb, 0, sbase, sbase + G_ASZ, tid);
    CP_COMMIT();
    load_chunk64(A, lda, B, ldb, 64, sbase + G_STG, sbase + G_STG + G_ASZ, tid);
    CP_COMMIT();
    CP_WAIT1();
    __syncthreads();

    uint32_t af0[4][4], bf0[8][2], af1[4][4], bf1[8][2];
    ld_frags(sbase + aOff, sbase + G_ASZ + bOff, af0, bf0);

    for (int c = 0; c < nk; c++) {
        const int s = c % 3;
        if (c + 2 < nk) {
            const int s2 = (c + 2) % 3;
            load_chunk64(A, lda, B, ldb, (c + 2) * 64,
                         sbase + s2 * G_STG, sbase + s2 * G_STG + G_ASZ, tid);
        }
        CP_COMMIT();

        const uint32_t aB = sbase + s * G_STG + aOff;
        const uint32_t bB = sbase + s * G_STG + G_ASZ + bOff;

        ld_frags(aB + 32, bB + 32, af1, bf1);       // ks1
        MMA_BATCH(af0, bf0);                        // ks0
        ld_frags(aB + 64, bB + 64, af0, bf0);       // ks2
        MMA_BATCH(af1, bf1);                        // ks1
        ld_frags(aB + 96, bB + 96, af1, bf1);       // ks3
        MMA_BATCH(af0, bf0);                        // ks2

        if (c + 1 < nk) {
            CP_WAIT1();
            __syncthreads();
            const int s1 = (c + 1) % 3;
            ld_frags(sbase + s1 * G_STG + aOff,
                     sbase + s1 * G_STG + G_ASZ + bOff, af0, bf0);  // next ks0
        }
        MMA_BATCH(af1, bf1);                        // ks3
    }
}

// ---------------- dense GEMM: C = A.Bt^T + bias (+relu) (+res) ---------
template <int OUT_HALF, int RELU>
__global__ __launch_bounds__(256, 1) void gemm_mma_kernel(
    const __half* __restrict__ A, int lda,
    const __half* __restrict__ Bt,
    const float* __restrict__ bias, const float* __restrict__ res,
    void* __restrict__ Cv, int ldc, int K)
{
    extern __shared__ char dyn[];
    const int mBase = blockIdx.y * 128;
    const int nBase = blockIdx.x * 256;
    const __half* Ab = A + (size_t)mBase * lda;
    const __half* Bb = Bt + (size_t)nBase * K;

    float acc[4][8][4];
    #pragma unroll
    for (int i = 0; i < 4; i++)
        #pragma unroll
        for (int j = 0; j < 8; j++)
            #pragma unroll
            for (int q = 0; q < 4; q++) acc[i][j][q] = 0.f;

    mma_mainloop(Ab, lda, Bb, K, K, acc, dyn);

    const int wid = threadIdx.x >> 5, lane = threadIdx.x & 31;
    const int wm = wid >> 2, wn = wid & 3;
    const int gid = lane >> 2, tig = lane & 3;
    const int mW = mBase + wm * 64;
    const int nW = nBase + wn * 64;

    #pragma unroll
    for (int mi = 0; mi < 4; mi++) {
        #pragma unroll
        for (int half_ = 0; half_ < 2; half_++) {
            const int row = mW + mi * 16 + gid + half_ * 8;
            #pragma unroll
            for (int ni = 0; ni < 8; ni++) {
                const int col = nW + ni * 8 + tig * 2;
                float v0 = acc[mi][ni][half_ * 2 + 0] + bias[col];
                float v1 = acc[mi][ni][half_ * 2 + 1] + bias[col + 1];
                if (RELU) { v0 = fmaxf(v0, 0.f); v1 = fmaxf(v1, 0.f); }
                if (OUT_HALF) {
                    __half* cRow = (__half*)Cv + (size_t)row * ldc;
                    *reinterpret_cast<__half2*>(cRow + col) = __floats2half2_rn(v0, v1);
                } else {
                    float* cRow = (float*)Cv + (size_t)row * ldc;
                    if (res) {
                        const float* rRow = res + (size_t)row * ldc;
                        v0 += rRow[col]; v1 += rRow[col + 1];
                    }
                    *reinterpret_cast<float2*>(cRow + col) = make_float2(v0, v1);
                }
            }
        }
    }
}

// ---------------- fused flash attention (V transposed via ldmatrix.trans)
__global__ __launch_bounds__(256) void flash_kernel(
    const __half* __restrict__ qkv,
    const int* __restrict__ mask, __half* __restrict__ ctx)
{
    extern __shared__ char dyn[];
    const uint32_t sb = smem_u32(dyn);
    float* sMask = (float*)(dyn + 2 * (QSZ + 2 * KSZ + 2 * VSZ));

    const int bh = blockIdx.y, b = bh >> 4, h = bh & 15;
    const int mBase = blockIdx.x * 128;
    const int tid = threadIdx.x, wid = tid >> 5, lane = tid & 31;
    const int gid = lane >> 2, tig = lane & 3;

    #pragma unroll
    for (int it = 0; it < 4; it++) {
        const int i = tid + it * 256;
        sMask[i] = (mask[b * SSZ + i] == 0) ? -60000.f : 0.f;
    }

    {
        const __half* Qg = qkv + (size_t)(b * SSZ + mBase) * QKVLD + h * 64;
        #pragma unroll
        for (int it = 0; it < 4; it++) {
            const int idx = tid + it * 256;
            const int r = idx >> 3, c = idx & 7;
            cpasync16(sb + (uint32_t)(r * LDQ + c * 8) * 2,
                      Qg + (size_t)r * QKVLD + c * 8);
        }
    }
    const __half* Kg0 = qkv + (size_t)(b * SSZ) * QKVLD + 1024 + h * 64;
    const __half* Vg0 = qkv + (size_t)(b * SSZ) * QKVLD + 2048 + h * 64;
    auto load_kv = [&](int stage, int t) {
        const __half* Kg = Kg0 + (size_t)(t * 128) * QKVLD;
        const uint32_t kS = sb + (uint32_t)((QSZ + stage * KSZ) * 2);
        #pragma unroll
        for (int it = 0; it < 4; it++) {
            const int idx = tid + it * 256;
            const int r = idx >> 3, c = idx & 7;
            cpasync16(kS + (uint32_t)(r * LDK + c * 8) * 2,
                      Kg + (size_t)r * QKVLD + c * 8);
        }
        const __half* Vg = Vg0 + (size_t)(t * 128) * QKVLD;
        const uint32_t vS = sb + (uint32_t)((QSZ + 2 * KSZ + stage * VSZ) * 2);
        #pragma unroll
        for (int it = 0; it < 4; it++) {
            const int idx = tid + it * 256;
            const int r = idx >> 3, c = idx & 7;
            cpasync16(vS + (uint32_t)(r * LDV + c * 8) * 2,
                      Vg + (size_t)r * QKVLD + c * 8);
        }
    };
    load_kv(0, 0);
    CP_COMMIT();

    const uint32_t aOffQ = (uint32_t)(((wid * 16 + (lane & 15)) * LDQ + ((lane >> 4) << 3)) * 2);
    const uint32_t bOffK = (uint32_t)((((lane & 7) + ((lane >> 4) << 3)) * LDK + (((lane >> 3) & 1) << 3)) * 2);
    const uint32_t bOffVt = (uint32_t)(((lane & 15) * LDV + ((lane >> 4) << 3)) * 2);

    uint32_t qf[4][4];
    float oacc[8][4];
    #pragma unroll
    for (int i = 0; i < 8; i++)
        #pragma unroll
        for (int q = 0; q < 4; q++) oacc[i][q] = 0.f;
    float m0 = -1e30f, m1 = -1e30f, l0 = 0.f, l1 = 0.f;

    for (int t = 0; t < 8; t++) {
        __syncthreads();
        if (t < 7) { load_kv((t + 1) & 1, t + 1); CP_COMMIT(); CP_WAIT1(); }
        else       { CP_WAIT0(); }
        __syncthreads();

        if (t == 0) {
            #pragma unroll
            for (int ks = 0; ks < 4; ks++)
                ldsm4(sb + aOffQ + ks * 32,
                      qf[ks][0], qf[ks][1], qf[ks][2], qf[ks][3]);
        }

        float sacc[16][4];
        #pragma unroll
        for (int ni = 0; ni < 16; ni++)
            #pragma unroll
            for (int q = 0; q < 4; q++) sacc[ni][q] = 0.f;

        const uint32_t kb = sb + (uint32_t)((QSZ + (t & 1) * KSZ) * 2) + bOffK;
        #pragma unroll
        for (int ks = 0; ks < 4; ks++) {
            uint32_t bfr[16][2];
            #pragma unroll
            for (int np = 0; np < 8; np++)
                ldsm4(kb + ks * 32 + (uint32_t)(np * 16 * LDK) * 2,
                      bfr[2 * np][0], bfr[2 * np][1],
                      bfr[2 * np + 1][0], bfr[2 * np + 1][1]);
            #pragma unroll
            for (int ni = 0; ni < 16; ni++)
                mma_f16(sacc[ni], qf[ks], bfr[ni]);
        }

        float tm0 = -1e30f, tm1 = -1e30f;
        #pragma unroll
        for (int ni = 0; ni < 16; ni++) {
            const int colb = t * 128 + ni * 8 + 2 * tig;
            const float ma = sMask[colb], mb = sMask[colb + 1];
            sacc[ni][0] = sacc[ni][0] * 0.125f + ma;
            sacc[ni][1] = sacc[ni][1] * 0.125f + mb;
            sacc[ni][2] = sacc[ni][2] * 0.125f + ma;
            sacc[ni][3] = sacc[ni][3] * 0.125f + mb;
            tm0 = fmaxf(tm0, fmaxf(sacc[ni][0], sacc[ni][1]));
            tm1 = fmaxf(tm1, fmaxf(sacc[ni][2], sacc[ni][3]));
        }
        tm0 = fmaxf(tm0, __shfl_xor_sync(0xffffffffu, tm0, 1));
        tm0 = fmaxf(tm0, __shfl_xor_sync(0xffffffffu, tm0, 2));
        tm1 = fmaxf(tm1, __shfl_xor_sync(0xffffffffu, tm1, 1));
        tm1 = fmaxf(tm1, __shfl_xor_sync(0xffffffffu, tm1, 2));

        const float mn0 = fmaxf(m0, tm0), mn1 = fmaxf(m1, tm1);
        const float c0 = __expf(m0 - mn0), c1 = __expf(m1 - mn1);
        m0 = mn0; m1 = mn1;

        float ls0 = 0.f, ls1 = 0.f;
        #pragma unroll
        for (int ni = 0; ni < 16; ni++) {
            sacc[ni][0] = __expf(sacc[ni][0] - m0);
            sacc[ni][1] = __expf(sacc[ni][1] - m0);
            sacc[ni][2] = __expf(sacc[ni][2] - m1);
            sacc[ni][3] = __expf(sacc[ni][3] - m1);
            ls0 += sacc[ni][0] + sacc[ni][1];
            ls1 += sacc[ni][2] + sacc[ni][3];
        }
        l0 = l0 * c0 + ls0;
        l1 = l1 * c1 + ls1;
        #pragma unroll
        for (int ni = 0; ni < 8; ni++) {
            oacc[ni][0] *= c0; oacc[ni][1] *= c0;
            oacc[ni][2] *= c1; oacc[ni][3] *= c1;
        }

        const uint32_t vb = sb + (uint32_t)((QSZ + 2 * KSZ + (t & 1) * VSZ) * 2) + bOffVt;
        #pragma unroll
        for (int j = 0; j < 8; j++) {
            uint32_t pf[4];
            {
                __half2 p0 = __floats2half2_rn(sacc[2 * j][0],     sacc[2 * j][1]);
                __half2 p1 = __floats2half2_rn(sacc[2 * j][2],     sacc[2 * j][3]);
                __half2 p2 = __floats2half2_rn(sacc[2 * j + 1][0], sacc[2 * j + 1][1]);
                __half2 p3 = __floats2half2_rn(sacc[2 * j + 1][2], sacc[2 * j + 1][3]);
                pf[0] = *reinterpret_cast<uint32_t*>(&p0);
                pf[1] = *reinterpret_cast<uint32_t*>(&p1);
                pf[2] = *reinterpret_cast<uint32_t*>(&p2);
                pf[3] = *reinterpret_cast<uint32_t*>(&p3);
            }
            uint32_t bfr2[8][2];
            #pragma unroll
            for (int np = 0; np < 4; np++)
                ldsm4t(vb + (uint32_t)((j * 16 * LDV + np * 16) * 2),
                       bfr2[2 * np][0], bfr2[2 * np][1],
                       bfr2[2 * np + 1][0], bfr2[2 * np + 1][1]);
            #pragma unroll
            for (int ni = 0; ni < 8; ni++)
                mma_f16(oacc[ni], pf, bfr2[ni]);
        }
    }

    l0 += __shfl_xor_sync(0xffffffffu, l0, 1);
    l0 += __shfl_xor_sync(0xffffffffu, l0, 2);
    l1 += __shfl_xor_sync(0xffffffffu, l1, 1);
    l1 += __shfl_xor_sync(0xffffffffu, l1, 2);
    const float inv0 = 1.f / l0, inv1 = 1.f / l1;

    const int row0 = mBase + wid * 16 + gid;
    __half* o0 = ctx + (size_t)(b * SSZ + row0) * DDM + h * 64;
    __half* o1 = o0 + 8 * DDM;
    #pragma unroll
    for (int ni = 0; ni < 8; ni++) {
        const int col = ni * 8 + 2 * tig;
        *reinterpret_cast<__half2*>(o0 + col) =
            __floats2half2_rn(oacc[ni][0] * inv0, oacc[ni][1] * inv0);
        *reinterpret_cast<__half2*>(o1 + col) =
            __floats2half2_rn(oacc[ni][2] * inv1, oacc[ni][3] * inv1);
    }
}

// ---------------- LayerNorm (ddof=1, eps on std, scalar a/b), half out --
__global__ __launch_bounds__(256) void ln_kernel(const float* __restrict__ x,
                                                 __half* __restrict__ y,
                                                 const float* __restrict__ alpha,
                                                 const float* __restrict__ beta)
{
    __shared__ float red[256];
    const int row = blockIdx.x, tid = threadIdx.x;
    const float* xr = x + (size_t)row * DDM;
    __half* yr = y + (size_t)row * DDM;

    float4 v = reinterpret_cast<const float4*>(xr)[tid];
    red[tid] = v.x + v.y + v.z + v.w; __syncthreads();
    for (int o = 128; o > 0; o >>= 1) { if (tid < o) red[tid] += red[tid + o]; __syncthreads(); }
    const float mean = red[0] * (1.0f / DDM);
    __syncthreads();

    float4 d = make_float4(v.x - mean, v.y - mean, v.z - mean, v.w - mean);
    red[tid] = d.x * d.x + d.y * d.y + d.z * d.z + d.w * d.w; __syncthreads();
    for (int o = 128; o > 0; o >>= 1) { if (tid < o) red[tid] += red[tid + o]; __syncthreads(); }
    const float stdv = sqrtf(red[0] * (1.0f / (DDM - 1)));
    const float a = alpha[0], bta = beta[0];
    const float inv = a / (stdv + 1e-6f);

    __half2 o0 = __floats2half2_rn(d.x * inv + bta, d.y * inv + bta);
    __half2 o1 = __floats2half2_rn(d.z * inv + bta, d.w * inv + bta);
    uint2 pk;
    pk.x = *reinterpret_cast<uint32_t*>(&o0);
    pk.y = *reinterpret_cast<uint32_t*>(&o1);
    reinterpret_cast<uint2*>(yr)[tid] = pk;
}

// ---------------- weight transpose: QKV weights + bias concat (critical) -
__global__ void wtrans_qkv_kernel(const float* __restrict__ wq, const float* __restrict__ wk,
                                  const float* __restrict__ wv,
                                  const float* __restrict__ bq, const float* __restrict__ bk,
                                  const float* __restrict__ bv,
                                  __half* __restrict__ wqkvt, float* __restrict__ bqkv)
{
    __shared__ float t[32][33];
    int tIdx = blockIdx.x;
    if (tIdx >= 3072) {
        const int i = (tIdx - 3072) * 256 + threadIdx.y * 32 + threadIdx.x;
        if (i < 1024) bqkv[i] = bq[i];
        else if (i < 2048) bqkv[i] = bk[i - 1024];
        else bqkv[i] = bv[i - 2048];
        return;
    }
    const int m = tIdx >> 10;
    const float* src = (m == 0) ? wq : (m == 1) ? wk : wv;
    __half* dst = wqkvt + (size_t)m * 1024 * 1024;
    tIdx &= 1023;
    const int c0 = (tIdx & 31) * 32, r0 = (tIdx >> 5) * 32;
    const int tx = threadIdx.x, ty = threadIdx.y;
    #pragma unroll
    for (int i = ty; i < 32; i += 8)
        t[i][tx] = src[(size_t)(r0 + i) * 1024 + c0 + tx];
    __syncthreads();
    #pragma unroll
    for (int i = ty; i < 32; i += 8)
        dst[(size_t)(c0 + i) * 1024 + r0 + tx] = __float2half_rn(t[tx][i]);
}

// ---------------- weight transpose: wo/w1/w2 (off critical path) ---------
__global__ void wtrans_rest_kernel(const float* __restrict__ wo,
                                   const float* __restrict__ w1, const float* __restrict__ w2,
                                   __half* __restrict__ wot,
                                   __half* __restrict__ w1t, __half* __restrict__ w2t)
{
    __shared__ float t[32][33];
    int tIdx = blockIdx.x;
    const float* src; __half* dst; int R, C;
    if (tIdx < 1024) {
        src = wo; dst = wot; R = 1024; C = 1024;
    } else if (tIdx < 5120) {
        src = w1; dst = w1t; R = 1024; C = 4096; tIdx -= 1024;
    } else {
        src = w2; dst = w2t; R = 4096; C = 1024; tIdx -= 5120;
    }
    const int nCx = C >> 5;
    const int c0 = (tIdx % nCx) * 32, r0 = (tIdx / nCx) * 32;
    const int tx = threadIdx.x, ty = threadIdx.y;
    #pragma unroll
    for (int i = ty; i < 32; i += 8)
        t[i][tx] = src[(size_t)(r0 + i) * C + c0 + tx];
    __syncthreads();
    #pragma unroll
    for (int i = ty; i < 32; i += 8)
        dst[(size_t)(c0 + i) * R + r0 + tx] = __float2half_rn(t[tx][i]);
}

// ---------------- launch ----------------
extern "C" void kernel_launch(void* const* d_in, const int* in_sizes, int n_in,
                              void* d_out, int out_size)
{
    const float* x      = (const float*)d_in[0];
    const int*   mask   = (const int*)  d_in[1];
    const float* wq     = (const float*)d_in[2];
    const float* bq     = (const float*)d_in[3];
    const float* wk     = (const float*)d_in[4];
    const float* bk     = (const float*)d_in[5];
    const float* wv     = (const float*)d_in[6];
    const float* bv     = (const float*)d_in[7];
    const float* wo     = (const float*)d_in[8];
    const float* bo     = (const float*)d_in[9];
    const float* w1     = (const float*)d_in[10];
    const float* b1     = (const float*)d_in[11];
    const float* w2     = (const float*)d_in[12];
    const float* b2     = (const float*)d_in[13];
    const float* alpha1 = (const float*)d_in[14];
    const float* beta1  = (const float*)d_in[15];
    const float* alpha2 = (const float*)d_in[16];
    const float* beta2  = (const float*)d_in[17];
    float* out = (float*)d_out;

    cudaFuncSetAttribute((const void*)gemm_mma_kernel<1, 0>, cudaFuncAttributeMaxDynamicSharedMemorySize, G_SMEM);
    cudaFuncSetAttribute((const void*)gemm_mma_kernel<1, 1>, cudaFuncAttributeMaxDynamicSharedMemorySize, G_SMEM);
    cudaFuncSetAttribute((const void*)gemm_mma_kernel<0, 0>, cudaFuncAttributeMaxDynamicSharedMemorySize, G_SMEM);
    cudaFuncSetAttribute((const void*)flash_kernel,          cudaFuncAttributeMaxDynamicSharedMemorySize, FL_SMEM);

    __half *xn, *qkv, *ctx, *ff, *wqkvt, *wot, *w1t, *w2t;
    float *x1, *bqkv;
    cudaGetSymbolAddress((void**)&xn,    g_xn);
    cudaGetSymbolAddress((void**)&qkv,   g_qkv);
    cudaGetSymbolAddress((void**)&ctx,   g_ctx);
    cudaGetSymbolAddress((void**)&x1,    g_x1);
    cudaGetSymbolAddress((void**)&ff,    g_ff);
    cudaGetSymbolAddress((void**)&wqkvt, g_wqkvt);
    cudaGetSymbolAddress((void**)&wot,   g_wot);
    cudaGetSymbolAddress((void**)&w1t,   g_w1t);
    cudaGetSymbolAddress((void**)&w2t,   g_w2t);
    cudaGetSymbolAddress((void**)&bqkv,  g_bqkv);

    static cudaStream_t sSide = nullptr;
    static cudaEvent_t evFork = nullptr, evJoin = nullptr;
    if (sSide == nullptr) {
        cudaStreamCreateWithFlags(&sSide, cudaStreamNonBlocking);
        cudaEventCreateWithFlags(&evFork, cudaEventDisableTiming);
        cudaEventCreateWithFlags(&evJoin, cudaEventDisableTiming);
    }

    dim3 tb(32, 8);
    // fork: wo/w1/w2 transposes on side stream, overlapped with main chain
    cudaEventRecord(evFork, 0);
    cudaStreamWaitEvent(sSide, evFork, 0);
    wtrans_rest_kernel<<<9216, tb, 0, sSide>>>(wo, w1, w2, wot, w1t, w2t);
    cudaEventRecord(evJoin, sSide);

    // main stream (critical path)
    wtrans_qkv_kernel<<<3072 + 12, tb>>>(wq, wk, wv, bq, bk, bv, wqkvt, bqkv);
    ln_kernel<<<ROWS, 256>>>(x, xn, alpha1, beta1);
    gemm_mma_kernel<1, 0><<<dim3(12, 32), 256, G_SMEM>>>(xn, DDM, wqkvt, bqkv,
                                                         nullptr, qkv, QKVLD, DDM);
    flash_kernel<<<dim3(8, BHH), 256, FL_SMEM>>>(qkv, mask, ctx);

    // join before WO GEMM (needs wot)
    cudaStreamWaitEvent(0, evJoin, 0);
    gemm_mma_kernel<0, 0><<<dim3(4, 32), 256, G_SMEM>>>(ctx, DDM, wot, bo,
                                                        x, x1, DDM, DDM);
    ln_kernel<<<ROWS, 256>>>(x1, xn, alpha2, beta2);
    gemm_mma_kernel<1, 1><<<dim3(16, 32), 256, G_SMEM>>>(xn, DDM, w1t, b1,
                                                         nullptr, ff, DFF, DDM);
    gemm_mma_kernel<0, 0><<<dim3(4, 32), 256, G_SMEM>>>(ff, DFF, w2t, b2,
                                                        x1, out, DDM, DFF);
}

// round 15
// speedup vs baseline: 1.0490x; 1.0490x over previous
#include <cuda_runtime.h>
#include <cuda_fp16.h>
#include <cstdint>

// ---------------- problem dims ----------------
#define BBX   4
#define SSZ   1024
#define DDM   1024
#define HHX   16
#define DFF   4096
#define ROWS  4096          // BBX*SSZ
#define BHH   64            // BBX*HHX
#define QKVLD 3072
#define SAW   72            // GEMM smem stride (halfs) for BK=64

// flash-attention smem strides (halfs)
#define LDQ   72
#define LDK   72
#define LDV   72            // V staged [s][d]; transposed in ldmatrix
#define QSZ   (128 * LDQ)
#define KSZ   (128 * LDK)
#define VSZ   (128 * LDV)
#define FL_SMEM (2 * (QSZ + 2 * KSZ + 2 * VSZ) + 4096)   // 96256 bytes

// GEMM smem
#define G_ASZ (128 * SAW * 2)        // 18432 B
#define G_STG (2 * G_ASZ)            // 36864 B
#define G_SMEM (3 * G_STG)           // 110592 B

// ---------------- scratch (static device globals) ----------------
__device__ __half g_xn   [(size_t)ROWS * DDM];
__device__ __half g_qkv  [(size_t)ROWS * QKVLD];
__device__ __half g_ctx  [(size_t)ROWS * DDM];
__device__ float  g_x1   [(size_t)ROWS * DDM];
__device__ __half g_ff   [(size_t)ROWS * DFF];
__device__ __half g_wqkvt[(size_t)QKVLD * DDM];
__device__ __half g_wot  [(size_t)DDM * DDM];
__device__ __half g_w1t  [(size_t)DFF * DDM];
__device__ __half g_w2t  [(size_t)DDM * DFF];
__device__ float  g_bqkv [QKVLD];

// ---------------- helpers ----------------
__device__ __forceinline__ uint32_t smem_u32(const void* p) {
    uint32_t a;
    asm("{ .reg .u64 t; cvta.to.shared.u64 t, %1; cvt.u32.u64 %0, t; }"
        : "=r"(a) : "l"(p));
    return a;
}
__device__ __forceinline__ void cpasync16(uint32_t s, const void* g) {
    asm volatile("cp.async.cg.shared.global [%0], [%1], 16;" :: "r"(s), "l"(g));
}
#define CP_COMMIT() asm volatile("cp.async.commit_group;" ::: "memory")
#define CP_WAIT1()  asm volatile("cp.async.wait_group 1;" ::: "memory")
#define CP_WAIT0()  asm volatile("cp.async.wait_group 0;" ::: "memory")

__device__ __forceinline__ void ldsm4(uint32_t addr, uint32_t& r0, uint32_t& r1,
                                      uint32_t& r2, uint32_t& r3) {
    asm volatile("ldmatrix.sync.aligned.m8n8.x4.shared.b16 {%0,%1,%2,%3}, [%4];"
                 : "=r"(r0), "=r"(r1), "=r"(r2), "=r"(r3) : "r"(addr));
}
__device__ __forceinline__ void ldsm4t(uint32_t addr, uint32_t& r0, uint32_t& r1,
                                       uint32_t& r2, uint32_t& r3) {
    asm volatile("ldmatrix.sync.aligned.m8n8.x4.trans.shared.b16 {%0,%1,%2,%3}, [%4];"
                 : "=r"(r0), "=r"(r1), "=r"(r2), "=r"(r3) : "r"(addr));
}

__device__ __forceinline__ void mma_f16(float (&d)[4],
                                        const uint32_t (&a)[4],
                                        const uint32_t (&b)[2]) {
    asm volatile(
        "mma.sync.aligned.m16n8k16.row.col.f32.f16.f16.f32 "
        "{%0,%1,%2,%3},{%4,%5,%6,%7},{%8,%9},{%0,%1,%2,%3};"
        : "+f"(d[0]), "+f"(d[1]), "+f"(d[2]), "+f"(d[3])
        : "r"(a[0]), "r"(a[1]), "r"(a[2]), "r"(a[3]),
          "r"(b[0]), "r"(b[1]));
}

// ---------------- GEMM: cp.async tile loader (one BK=64 chunk, halfs) ----
__device__ __forceinline__ void load_chunk64(const __half* __restrict__ A, int lda,
                                             const __half* __restrict__ B, int ldb,
                                             int k0, uint32_t sA, uint32_t sB, int tid)
{
    #pragma unroll
    for (int it = 0; it < 4; it++) {
        const int idx = tid + it * 256;
        const int r = idx >> 3, c = idx & 7;
        cpasync16(sA + (uint32_t)(r * SAW + c * 8) * 2,
                  A + (size_t)r * lda + k0 + c * 8);
    }
    #pragma unroll
    for (int it = 0; it < 4; it++) {
        const int idx = tid + it * 256;
        const int r = idx >> 3, c = idx & 7;
        cpasync16(sB + (uint32_t)(r * SAW + c * 8) * 2,
                  B + (size_t)r * ldb + k0 + c * 8);
    }
}

// fragment loads for one k16 step (A 64 rows, B 32 rows per warp)
__device__ __forceinline__ void ld_frags(uint32_t aB, uint32_t bB,
                                         uint32_t (&af)[4][4], uint32_t (&bf)[4][2])
{
    #pragma unroll
    for (int mi = 0; mi < 4; mi++)
        ldsm4(aB + (uint32_t)(mi * 16 * SAW) * 2,
              af[mi][0], af[mi][1], af[mi][2], af[mi][3]);
    #pragma unroll
    for (int np = 0; np < 2; np++)
        ldsm4(bB + (uint32_t)(np * 16 * SAW) * 2,
              bf[2 * np][0], bf[2 * np][1],
              bf[2 * np + 1][0], bf[2 * np + 1][1]);
}

#define MMA_BATCH(af, bf)                               \
    _Pragma("unroll")                                   \
    for (int mi = 0; mi < 4; mi++)                      \
        _Pragma("unroll")                               \
        for (int ni = 0; ni < 4; ni++)                  \
            mma_f16(acc[mi][ni], (af)[mi], (bf)[ni]);

// ---------------- GEMM mainloop: BK=64, 3 stages, frag double buffer ----
__device__ __forceinline__ void mma_mainloop(const __half* __restrict__ A, int lda,
                                             const __half* __restrict__ B, int ldb,
                                             int K, float (&acc)[4][4][4], char* dyn)
{
    const int tid = threadIdx.x;
    const int wid = tid >> 5, lane = tid & 31;
    const int wm = wid >> 2, wn = wid & 3;
    const uint32_t sbase = smem_u32(dyn);

    const uint32_t aOff = (uint32_t)(((wm * 64 + (lane & 15)) * SAW + ((lane >> 4) << 3)) * 2);
    const uint32_t bOff = (uint32_t)(((wn * 32 + (lane & 7) + ((lane >> 4) << 3)) * SAW
                                      + (((lane >> 3) & 1) << 3)) * 2);

    const int nk = K >> 6;
    load_chunk64(A, lda, B, ldb, 0, sbase, sbase + G_ASZ, tid);
    CP_COMMIT();
    load_chunk64(A, lda, B, ldb, 64, sbase + G_STG, sbase + G_STG + G_ASZ, tid);
    CP_COMMIT();
    CP_WAIT1();
    __syncthreads();

    uint32_t af0[4][4], bf0[4][2], af1[4][4], bf1[4][2];
    ld_frags(sbase + aOff, sbase + G_ASZ + bOff, af0, bf0);

    for (int c = 0; c < nk; c++) {
        const int s = c % 3;
        if (c + 2 < nk) {
            const int s2 = (c + 2) % 3;
            load_chunk64(A, lda, B, ldb, (c + 2) * 64,
                         sbase + s2 * G_STG, sbase + s2 * G_STG + G_ASZ, tid);
        }
        CP_COMMIT();

        const uint32_t aB = sbase + s * G_STG + aOff;
        const uint32_t bB = sbase + s * G_STG + G_ASZ + bOff;

        ld_frags(aB + 32, bB + 32, af1, bf1);       // ks1
        MMA_BATCH(af0, bf0);                        // ks0
        ld_frags(aB + 64, bB + 64, af0, bf0);       // ks2
        MMA_BATCH(af1, bf1);                        // ks1
        ld_frags(aB + 96, bB + 96, af1, bf1);       // ks3
        MMA_BATCH(af0, bf0);                        // ks2

        if (c + 1 < nk) {
            CP_WAIT1();
            __syncthreads();
            const int s1 = (c + 1) % 3;
            ld_frags(sbase + s1 * G_STG + aOff,
                     sbase + s1 * G_STG + G_ASZ + bOff, af0, bf0);  // next ks0
        }
        MMA_BATCH(af1, bf1);                        // ks3
    }
}

// ---------------- dense GEMM: C = A.Bt^T + bias (+relu) (+res) ---------
template <int OUT_HALF, int RELU>
__global__ __launch_bounds__(256, 2) void gemm_mma_kernel(
    const __half* __restrict__ A, int lda,
    const __half* __restrict__ Bt,
    const float* __restrict__ bias, const float* __restrict__ res,
    void* __restrict__ Cv, int ldc, int K)
{
    extern __shared__ char dyn[];
    const int mBase = blockIdx.y * 128;
    const int nBase = blockIdx.x * 128;
    const __half* Ab = A + (size_t)mBase * lda;
    const __half* Bb = Bt + (size_t)nBase * K;

    float acc[4][4][4];
    #pragma unroll
    for (int i = 0; i < 4; i++)
        #pragma unroll
        for (int j = 0; j < 4; j++)
            #pragma unroll
            for (int q = 0; q < 4; q++) acc[i][j][q] = 0.f;

    mma_mainloop(Ab, lda, Bb, K, K, acc, dyn);

    const int wid = threadIdx.x >> 5, lane = threadIdx.x & 31;
    const int wm = wid >> 2, wn = wid & 3;
    const int gid = lane >> 2, tig = lane & 3;
    const int mW = mBase + wm * 64;
    const int nW = nBase + wn * 32;

    #pragma unroll
    for (int mi = 0; mi < 4; mi++) {
        #pragma unroll
        for (int half_ = 0; half_ < 2; half_++) {
            const int row = mW + mi * 16 + gid + half_ * 8;
            #pragma unroll
            for (int ni = 0; ni < 4; ni++) {
                const int col = nW + ni * 8 + tig * 2;
                float v0 = acc[mi][ni][half_ * 2 + 0] + bias[col];
                float v1 = acc[mi][ni][half_ * 2 + 1] + bias[col + 1];
                if (RELU) { v0 = fmaxf(v0, 0.f); v1 = fmaxf(v1, 0.f); }
                if (OUT_HALF) {
                    __half* cRow = (__half*)Cv + (size_t)row * ldc;
                    *reinterpret_cast<__half2*>(cRow + col) = __floats2half2_rn(v0, v1);
                } else {
                    float* cRow = (float*)Cv + (size_t)row * ldc;
                    if (res) {
                        const float* rRow = res + (size_t)row * ldc;
                        v0 += rRow[col]; v1 += rRow[col + 1];
                    }
                    *reinterpret_cast<float2*>(cRow + col) = make_float2(v0, v1);
                }
            }
        }
    }
}

// ---------------- fused flash attention (V transposed via ldmatrix.trans)
__global__ __launch_bounds__(256) void flash_kernel(
    const __half* __restrict__ qkv,
    const int* __restrict__ mask, __half* __restrict__ ctx)
{
    extern __shared__ char dyn[];
    const uint32_t sb = smem_u32(dyn);
    float* sMask = (float*)(dyn + 2 * (QSZ + 2 * KSZ + 2 * VSZ));

    const int bh = blockIdx.y, b = bh >> 4, h = bh & 15;
    const int mBase = blockIdx.x * 128;
    const int tid = threadIdx.x, wid = tid >> 5, lane = tid & 31;
    const int gid = lane >> 2, tig = lane & 3;

    #pragma unroll
    for (int it = 0; it < 4; it++) {
        const int i = tid + it * 256;
        sMask[i] = (mask[b * SSZ + i] == 0) ? -60000.f : 0.f;
    }

    {
        const __half* Qg = qkv + (size_t)(b * SSZ + mBase) * QKVLD + h * 64;
        #pragma unroll
        for (int it = 0; it < 4; it++) {
            const int idx = tid + it * 256;
            const int r = idx >> 3, c = idx & 7;
            cpasync16(sb + (uint32_t)(r * LDQ + c * 8) * 2,
                      Qg + (size_t)r * QKVLD + c * 8);
        }
    }
    const __half* Kg0 = qkv + (size_t)(b * SSZ) * QKVLD + 1024 + h * 64;
    const __half* Vg0 = qkv + (size_t)(b * SSZ) * QKVLD + 2048 + h * 64;
    auto load_kv = [&](int stage, int t) {
        const __half* Kg = Kg0 + (size_t)(t * 128) * QKVLD;
        const uint32_t kS = sb + (uint32_t)((QSZ + stage * KSZ) * 2);
        #pragma unroll
        for (int it = 0; it < 4; it++) {
            const int idx = tid + it * 256;
            const int r = idx >> 3, c = idx & 7;
            cpasync16(kS + (uint32_t)(r * LDK + c * 8) * 2,
                      Kg + (size_t)r * QKVLD + c * 8);
        }
        const __half* Vg = Vg0 + (size_t)(t * 128) * QKVLD;
        const uint32_t vS = sb + (uint32_t)((QSZ + 2 * KSZ + stage * VSZ) * 2);
        #pragma unroll
        for (int it = 0; it < 4; it++) {
            const int idx = tid + it * 256;
            const int r = idx >> 3, c = idx & 7;
            cpasync16(vS + (uint32_t)(r * LDV + c * 8) * 2,
                      Vg + (size_t)r * QKVLD + c * 8);
        }
    };
    load_kv(0, 0);
    CP_COMMIT();

    const uint32_t aOffQ = (uint32_t)(((wid * 16 + (lane & 15)) * LDQ + ((lane >> 4) << 3)) * 2);
    const uint32_t bOffK = (uint32_t)((((lane & 7) + ((lane >> 4) << 3)) * LDK + (((lane >> 3) & 1) << 3)) * 2);
    const uint32_t bOffVt = (uint32_t)(((lane & 15) * LDV + ((lane >> 4) << 3)) * 2);

    uint32_t qf[4][4];
    float oacc[8][4];
    #pragma unroll
    for (int i = 0; i < 8; i++)
        #pragma unroll
        for (int q = 0; q < 4; q++) oacc[i][q] = 0.f;
    float m0 = -1e30f, m1 = -1e30f, l0 = 0.f, l1 = 0.f;

    for (int t = 0; t < 8; t++) {
        __syncthreads();
        if (t < 7) { load_kv((t + 1) & 1, t + 1); CP_COMMIT(); CP_WAIT1(); }
        else       { CP_WAIT0(); }
        __syncthreads();

        if (t == 0) {
            #pragma unroll
            for (int ks = 0; ks < 4; ks++)
                ldsm4(sb + aOffQ + ks * 32,
                      qf[ks][0], qf[ks][1], qf[ks][2], qf[ks][3]);
        }

        float sacc[16][4];
        #pragma unroll
        for (int ni = 0; ni < 16; ni++)
            #pragma unroll
            for (int q = 0; q < 4; q++) sacc[ni][q] = 0.f;

        const uint32_t kb = sb + (uint32_t)((QSZ + (t & 1) * KSZ) * 2) + bOffK;
        #pragma unroll
        for (int ks = 0; ks < 4; ks++) {
            uint32_t bfr[16][2];
            #pragma unroll
            for (int np = 0; np < 8; np++)
                ldsm4(kb + ks * 32 + (uint32_t)(np * 16 * LDK) * 2,
                      bfr[2 * np][0], bfr[2 * np][1],
                      bfr[2 * np + 1][0], bfr[2 * np + 1][1]);
            #pragma unroll
            for (int ni = 0; ni < 16; ni++)
                mma_f16(sacc[ni], qf[ks], bfr[ni]);
        }

        float tm0 = -1e30f, tm1 = -1e30f;
        #pragma unroll
        for (int ni = 0; ni < 16; ni++) {
            const int colb = t * 128 + ni * 8 + 2 * tig;
            const float ma = sMask[colb], mb = sMask[colb + 1];
            sacc[ni][0] = sacc[ni][0] * 0.125f + ma;
            sacc[ni][1] = sacc[ni][1] * 0.125f + mb;
            sacc[ni][2] = sacc[ni][2] * 0.125f + ma;
            sacc[ni][3] = sacc[ni][3] * 0.125f + mb;
            tm0 = fmaxf(tm0, fmaxf(sacc[ni][0], sacc[ni][1]));
            tm1 = fmaxf(tm1, fmaxf(sacc[ni][2], sacc[ni][3]));
        }
        tm0 = fmaxf(tm0, __shfl_xor_sync(0xffffffffu, tm0, 1));
        tm0 = fmaxf(tm0, __shfl_xor_sync(0xffffffffu, tm0, 2));
        tm1 = fmaxf(tm1, __shfl_xor_sync(0xffffffffu, tm1, 1));
        tm1 = fmaxf(tm1, __shfl_xor_sync(0xffffffffu, tm1, 2));

        const float mn0 = fmaxf(m0, tm0), mn1 = fmaxf(m1, tm1);
        const float c0 = __expf(m0 - mn0), c1 = __expf(m1 - mn1);
        m0 = mn0; m1 = mn1;

        float ls0 = 0.f, ls1 = 0.f;
        #pragma unroll
        for (int ni = 0; ni < 16; ni++) {
            sacc[ni][0] = __expf(sacc[ni][0] - m0);
            sacc[ni][1] = __expf(sacc[ni][1] - m0);
            sacc[ni][2] = __expf(sacc[ni][2] - m1);
            sacc[ni][3] = __expf(sacc[ni][3] - m1);
            ls0 += sacc[ni][0] + sacc[ni][1];
            ls1 += sacc[ni][2] + sacc[ni][3];
        }
        l0 = l0 * c0 + ls0;
        l1 = l1 * c1 + ls1;
        #pragma unroll
        for (int ni = 0; ni < 8; ni++) {
            oacc[ni][0] *= c0; oacc[ni][1] *= c0;
            oacc[ni][2] *= c1; oacc[ni][3] *= c1;
        }

        const uint32_t vb = sb + (uint32_t)((QSZ + 2 * KSZ + (t & 1) * VSZ) * 2) + bOffVt;
        #pragma unroll
        for (int j = 0; j < 8; j++) {
            uint32_t pf[4];
            {
                __half2 p0 = __floats2half2_rn(sacc[2 * j][0],     sacc[2 * j][1]);
                __half2 p1 = __floats2half2_rn(sacc[2 * j][2],     sacc[2 * j][3]);
                __half2 p2 = __floats2half2_rn(sacc[2 * j + 1][0], sacc[2 * j + 1][1]);
                __half2 p3 = __floats2half2_rn(sacc[2 * j + 1][2], sacc[2 * j + 1][3]);
                pf[0] = *reinterpret_cast<uint32_t*>(&p0);
                pf[1] = *reinterpret_cast<uint32_t*>(&p1);
                pf[2] = *reinterpret_cast<uint32_t*>(&p2);
                pf[3] = *reinterpret_cast<uint32_t*>(&p3);
            }
            uint32_t bfr2[8][2];
            #pragma unroll
            for (int np = 0; np < 4; np++)
                ldsm4t(vb + (uint32_t)((j * 16 * LDV + np * 16) * 2),
                       bfr2[2 * np][0], bfr2[2 * np][1],
                       bfr2[2 * np + 1][0], bfr2[2 * np + 1][1]);
            #pragma unroll
            for (int ni = 0; ni < 8; ni++)
                mma_f16(oacc[ni], pf, bfr2[ni]);
        }
    }

    l0 += __shfl_xor_sync(0xffffffffu, l0, 1);
    l0 += __shfl_xor_sync(0xffffffffu, l0, 2);
    l1 += __shfl_xor_sync(0xffffffffu, l1, 1);
    l1 += __shfl_xor_sync(0xffffffffu, l1, 2);
    const float inv0 = 1.f / l0, inv1 = 1.f / l1;

    const int row0 = mBase + wid * 16 + gid;
    __half* o0 = ctx + (size_t)(b * SSZ + row0) * DDM + h * 64;
    __half* o1 = o0 + 8 * DDM;
    #pragma unroll
    for (int ni = 0; ni < 8; ni++) {
        const int col = ni * 8 + 2 * tig;
        *reinterpret_cast<__half2*>(o0 + col) =
            __floats2half2_rn(oacc[ni][0] * inv0, oacc[ni][1] * inv0);
        *reinterpret_cast<__half2*>(o1 + col) =
            __floats2half2_rn(oacc[ni][2] * inv1, oacc[ni][3] * inv1);
    }
}

// ---------------- LayerNorm (ddof=1, eps on std, scalar a/b), half out --
__global__ __launch_bounds__(256) void ln_kernel(const float* __restrict__ x,
                                                 __half* __restrict__ y,
                                                 const float* __restrict__ alpha,
                                                 const float* __restrict__ beta)
{
    __shared__ float red[256];
    const int row = blockIdx.x, tid = threadIdx.x;
    const float* xr = x + (size_t)row * DDM;
    __half* yr = y + (size_t)row * DDM;

    float4 v = reinterpret_cast<const float4*>(xr)[tid];
    red[tid] = v.x + v.y + v.z + v.w; __syncthreads();
    for (int o = 128; o > 0; o >>= 1) { if (tid < o) red[tid] += red[tid + o]; __syncthreads(); }
    const float mean = red[0] * (1.0f / DDM);
    __syncthreads();

    float4 d = make_float4(v.x - mean, v.y - mean, v.z - mean, v.w - mean);
    red[tid] = d.x * d.x + d.y * d.y + d.z * d.z + d.w * d.w; __syncthreads();
    for (int o = 128; o > 0; o >>= 1) { if (tid < o) red[tid] += red[tid + o]; __syncthreads(); }
    const float stdv = sqrtf(red[0] * (1.0f / (DDM - 1)));
    const float a = alpha[0], bta = beta[0];
    const float inv = a / (stdv + 1e-6f);

    __half2 o0 = __floats2half2_rn(d.x * inv + bta, d.y * inv + bta);
    __half2 o1 = __floats2half2_rn(d.z * inv + bta, d.w * inv + bta);
    uint2 pk;
    pk.x = *reinterpret_cast<uint32_t*>(&o0);
    pk.y = *reinterpret_cast<uint32_t*>(&o1);
    reinterpret_cast<uint2*>(yr)[tid] = pk;
}

// ---------------- weight transpose: QKV weights + bias concat -----------
__global__ void wtrans_qkv_kernel(const float* __restrict__ wq, const float* __restrict__ wk,
                                  const float* __restrict__ wv,
                                  const float* __restrict__ bq, const float* __restrict__ bk,
                                  const float* __restrict__ bv,
                                  __half* __restrict__ wqkvt, float* __restrict__ bqkv)
{
    __shared__ float t[32][33];
    int tIdx = blockIdx.x;
    if (tIdx >= 3072) {
        const int i = (tIdx - 3072) * 256 + threadIdx.y * 32 + threadIdx.x;
        if (i < 1024) bqkv[i] = bq[i];
        else if (i < 2048) bqkv[i] = bk[i - 1024];
        else bqkv[i] = bv[i - 2048];
        return;
    }
    const int m = tIdx >> 10;
    const float* src = (m == 0) ? wq : (m == 1) ? wk : wv;
    __half* dst = wqkvt + (size_t)m * 1024 * 1024;
    tIdx &= 1023;
    const int c0 = (tIdx & 31) * 32, r0 = (tIdx >> 5) * 32;
    const int tx = threadIdx.x, ty = threadIdx.y;
    #pragma unroll
    for (int i = ty; i < 32; i += 8)
        t[i][tx] = src[(size_t)(r0 + i) * 1024 + c0 + tx];
    __syncthreads();
    #pragma unroll
    for (int i = ty; i < 32; i += 8)
        dst[(size_t)(c0 + i) * 1024 + r0 + tx] = __float2half_rn(t[tx][i]);
}

// ---------------- weight transpose: wo/w1/w2 (off critical path) ---------
__global__ void wtrans_rest_kernel(const float* __restrict__ wo,
                                   const float* __restrict__ w1, const float* __restrict__ w2,
                                   __half* __restrict__ wot,
                                   __half* __restrict__ w1t, __half* __restrict__ w2t)
{
    __shared__ float t[32][33];
    int tIdx = blockIdx.x;
    const float* src; __half* dst; int R, C;
    if (tIdx < 1024) {
        src = wo; dst = wot; R = 1024; C = 1024;
    } else if (tIdx < 5120) {
        src = w1; dst = w1t; R = 1024; C = 4096; tIdx -= 1024;
    } else {
        src = w2; dst = w2t; R = 4096; C = 1024; tIdx -= 5120;
    }
    const int nCx = C >> 5;
    const int c0 = (tIdx % nCx) * 32, r0 = (tIdx / nCx) * 32;
    const int tx = threadIdx.x, ty = threadIdx.y;
    #pragma unroll
    for (int i = ty; i < 32; i += 8)
        t[i][tx] = src[(size_t)(r0 + i) * C + c0 + tx];
    __syncthreads();
    #pragma unroll
    for (int i = ty; i < 32; i += 8)
        dst[(size_t)(c0 + i) * R + r0 + tx] = __float2half_rn(t[tx][i]);
}

// ---------------- launch ----------------
extern "C" void kernel_launch(void* const* d_in, const int* in_sizes, int n_in,
                              void* d_out, int out_size)
{
    const float* x      = (const float*)d_in[0];
    const int*   mask   = (const int*)  d_in[1];
    const float* wq     = (const float*)d_in[2];
    const float* bq     = (const float*)d_in[3];
    const float* wk     = (const float*)d_in[4];
    const float* bk     = (const float*)d_in[5];
    const float* wv     = (const float*)d_in[6];
    const float* bv     = (const float*)d_in[7];
    const float* wo     = (const float*)d_in[8];
    const float* bo     = (const float*)d_in[9];
    const float* w1     = (const float*)d_in[10];
    const float* b1     = (const float*)d_in[11];
    const float* w2     = (const float*)d_in[12];
    const float* b2     = (const float*)d_in[13];
    const float* alpha1 = (const float*)d_in[14];
    const float* beta1  = (const float*)d_in[15];
    const float* alpha2 = (const float*)d_in[16];
    const float* beta2  = (const float*)d_in[17];
    float* out = (float*)d_out;

    cudaFuncSetAttribute((const void*)gemm_mma_kernel<1, 0>, cudaFuncAttributeMaxDynamicSharedMemorySize, G_SMEM);
    cudaFuncSetAttribute((const void*)gemm_mma_kernel<1, 1>, cudaFuncAttributeMaxDynamicSharedMemorySize, G_SMEM);
    cudaFuncSetAttribute((const void*)gemm_mma_kernel<0, 0>, cudaFuncAttributeMaxDynamicSharedMemorySize, G_SMEM);
    cudaFuncSetAttribute((const void*)flash_kernel,          cudaFuncAttributeMaxDynamicSharedMemorySize, FL_SMEM);

    __half *xn, *qkv, *ctx, *ff, *wqkvt, *wot, *w1t, *w2t;
    float *x1, *bqkv;
    cudaGetSymbolAddress((void**)&xn,    g_xn);
    cudaGetSymbolAddress((void**)&qkv,   g_qkv);
    cudaGetSymbolAddress((void**)&ctx,   g_ctx);
    cudaGetSymbolAddress((void**)&x1,    g_x1);
    cudaGetSymbolAddress((void**)&ff,    g_ff);
    cudaGetSymbolAddress((void**)&wqkvt, g_wqkvt);
    cudaGetSymbolAddress((void**)&wot,   g_wot);
    cudaGetSymbolAddress((void**)&w1t,   g_w1t);
    cudaGetSymbolAddress((void**)&w2t,   g_w2t);
    cudaGetSymbolAddress((void**)&bqkv,  g_bqkv);

    static cudaStream_t sSide = nullptr;
    static cudaEvent_t evFork = nullptr, evLn = nullptr, evJoin = nullptr;
    if (sSide == nullptr) {
        cudaStreamCreateWithFlags(&sSide, cudaStreamNonBlocking);
        cudaEventCreateWithFlags(&evFork, cudaEventDisableTiming);
        cudaEventCreateWithFlags(&evLn,   cudaEventDisableTiming);
        cudaEventCreateWithFlags(&evJoin, cudaEventDisableTiming);
    }

    dim3 tb(32, 8);
    // fork: LN1 (short) then wo/w1/w2 transposes on side stream
    cudaEventRecord(evFork, 0);
    cudaStreamWaitEvent(sSide, evFork, 0);
    ln_kernel<<<ROWS, 256, 0, sSide>>>(x, xn, alpha1, beta1);
    cudaEventRecord(evLn, sSide);
    wtrans_rest_kernel<<<9216, tb, 0, sSide>>>(wo, w1, w2, wot, w1t, w2t);
    cudaEventRecord(evJoin, sSide);

    // main stream: QKV weight transpose runs concurrently with LN1
    wtrans_qkv_kernel<<<3072 + 12, tb>>>(wq, wk, wv, bq, bk, bv, wqkvt, bqkv);
    cudaStreamWaitEvent(0, evLn, 0);
    gemm_mma_kernel<1, 0><<<dim3(24, 32), 256, G_SMEM>>>(xn, DDM, wqkvt, bqkv,
                                                         nullptr, qkv, QKVLD, DDM);
    flash_kernel<<<dim3(8, BHH), 256, FL_SMEM>>>(qkv, mask, ctx);

    // join before WO GEMM (needs wot)
    cudaStreamWaitEvent(0, evJoin, 0);
    gemm_mma_kernel<0, 0><<<dim3(8, 32), 256, G_SMEM>>>(ctx, DDM, wot, bo,
                                                        x, x1, DDM, DDM);
    ln_kernel<<<ROWS, 256>>>(x1, xn, alpha2, beta2);
    gemm_mma_kernel<1, 1><<<dim3(32, 32), 256, G_SMEM>>>(xn, DDM, w1t, b1,
                                                         nullptr, ff, DFF, DDM);
    gemm_mma_kernel<0, 0><<<dim3(8, 32), 256, G_SMEM>>>(ff, DFF, w2t, b2,
                                                        x1, out, DDM, DFF);
}